// round 8
// baseline (speedup 1.0000x reference)
#include <cuda_runtime.h>
#include <cstdint>

// CRF_14379550507279 fixed shapes:
//   emissions (B=512, S=2048, T=32) f32, tags (B,S) i32, mask (B,S) f32,
//   transitions (32,32) f32. Output: scalar f32.
//
// total = sum_{all b,s,t} mask[b,s]*em[b,s,t]                              (phase 2)
//       + sum_b [ (1-mask[b,0])*sum_t em[b,0,t] + sum_t trans[tags[b,0],t] ] (phase 1b)
//       + 32 * sum_{b,s>=1} trans[tags[b,s-1],tags[b,s]] * mask[b,s]        (phase 1a)

#define NTAGS 32
#define B_DIM 512
#define S_DIM 2048
#define BS_ROWS (B_DIM * S_DIM)          // 1048576 rows of 32 floats (128 B)
#define GRID 1184                        // 148 SMs * 8 CTAs
#define BLOCK 128
#define NT (GRID * BLOCK)

#define TILE_CHUNKS 512                  // float4 chunks per tile (8 KB)
#define TILE_BYTES  8192
#define TILE_ROWS   64                   // emission rows per tile
#define N_TILES     (BS_ROWS * 8 / TILE_CHUNKS)   // 16384
#define STAGES      3

__device__ double g_acc = 0.0;
__device__ unsigned int g_count = 0;

__device__ __forceinline__ float hsum4(float4 v) {
    return (v.x + v.y) + (v.z + v.w);
}

__device__ __forceinline__ uint32_t smem_u32(const void* p) {
    uint32_t a;
    asm("{ .reg .u64 t; cvta.to.shared.u64 t, %1; cvt.u32.u64 %0, t; }"
        : "=r"(a) : "l"(p));
    return a;
}

__device__ __forceinline__ void mbar_init(uint32_t mbar, uint32_t cnt) {
    asm volatile("mbarrier.init.shared.b64 [%0], %1;" :: "r"(mbar), "r"(cnt) : "memory");
}

__device__ __forceinline__ void mbar_expect_tx(uint32_t mbar, uint32_t bytes) {
    asm volatile("mbarrier.arrive.expect_tx.shared.b64 _, [%0], %1;"
                 :: "r"(mbar), "r"(bytes) : "memory");
}

__device__ __forceinline__ void mbar_wait(uint32_t mbar, uint32_t parity) {
    uint32_t done;
    asm volatile(
        "{\n\t.reg .pred p;\n\t"
        "mbarrier.try_wait.parity.acquire.cta.shared::cta.b64 p, [%1], %2;\n\t"
        "selp.b32 %0, 1, 0, p;\n\t}"
        : "=r"(done) : "r"(mbar), "r"(parity) : "memory");
    if (!done) {
        asm volatile(
            "{\n\t.reg .pred P1;\n\t"
            "W_%=:\n\t"
            "mbarrier.try_wait.parity.acquire.cta.shared::cta.b64 P1, [%0], %1, 0x989680;\n\t"
            "@P1 bra.uni D_%=;\n\t"
            "bra.uni W_%=;\n\t"
            "D_%=:\n\t}"
            :: "r"(mbar), "r"(parity) : "memory");
    }
}

__device__ __forceinline__ void bulk_g2s(uint32_t dst, const void* src,
                                         uint32_t bytes, uint32_t mbar) {
    asm volatile(
        "cp.async.bulk.shared::cluster.global.mbarrier::complete_tx::bytes "
        "[%0], [%1], %2, [%3];"
        :: "r"(dst), "l"(src), "r"(bytes), "r"(mbar) : "memory");
}

__global__ void __launch_bounds__(BLOCK, 8) crf_fused_kernel(
    const float4* __restrict__ em4,    // B*S*8 float4 chunks
    const int* __restrict__ tags,      // B*S
    const float* __restrict__ mask,    // B*S
    const float* __restrict__ trans,   // 32*32
    float* __restrict__ out)
{
    __shared__ __align__(128) float4 s_buf[STAGES][TILE_CHUNKS]; // 24 KB
    __shared__ float s_trans[NTAGS * NTAGS];                     // 4 KB
    __shared__ __align__(8) unsigned long long s_mbar[STAGES];
    __shared__ float warp_sums[BLOCK / 32];

    const int tid = threadIdx.x;
    const int gtid = blockIdx.x * BLOCK + tid;

    for (int i = tid; i < NTAGS * NTAGS; i += BLOCK)
        s_trans[i] = trans[i];
    if (tid < STAGES)
        mbar_init(smem_u32(&s_mbar[tid]), 1);
    __syncthreads();

    // Tile schedule: this CTA owns tiles t0, t0+GRID, ...
    const int t0 = blockIdx.x;
    const int n_tiles = (N_TILES - t0 + GRID - 1) / GRID;   // 13 or 14

    // ---- Kick off the TMA pipeline first (prologue), so phase 1 overlaps it.
    if (tid == 0) {
        const int p = n_tiles < STAGES ? n_tiles : STAGES;
        for (int i = 0; i < p; i++) {
            const uint32_t mb = smem_u32(&s_mbar[i]);
            mbar_expect_tx(mb, TILE_BYTES);
            bulk_g2s(smem_u32(&s_buf[i][0]),
                     em4 + (size_t)(t0 + i * GRID) * TILE_CHUNKS,
                     TILE_BYTES, mb);
        }
    }

    float acc = 0.0f;

    // ---- Phase 1a: transition steps, branch-free; overlaps in-flight TMA.
    for (int row = gtid; row < BS_ROWS; row += NT) {
        const int s = row & (S_DIM - 1);
        const int tc = __ldg(&tags[row]);
        const int tp = __ldg(&tags[(row > 0) ? (row - 1) : 0]);
        const float w = (s == 0) ? 0.0f : __ldg(&mask[row]);
        acc += (float)NTAGS * s_trans[tp * NTAGS + tc] * w;
    }

    // ---- Phase 1b: s==0 specials (512 terms, one thread per batch row).
    if (gtid < B_DIM) {
        const int row = gtid * S_DIM;
        const int tc = __ldg(&tags[row]);
        const float m = __ldg(&mask[row]);
        float ts = 0.0f;
        #pragma unroll
        for (int t = 0; t < NTAGS; t++) ts += s_trans[tc * NTAGS + t];
        float es = 0.0f;
        const float4* p = em4 + (size_t)row * 8;
        #pragma unroll
        for (int i = 0; i < 8; i++) es += hsum4(__ldg(p + i));
        // phase 2 weights this row by mask[b,0]; reference wants weight 1
        acc += ts + (1.0f - m) * es;
    }

    // ---- Phase 2: consume TMA-staged tiles.
    {
        int s = 0, ph = 0;
        for (int i = 0; i < n_tiles; i++) {
            const int tile = t0 + i * GRID;
            mbar_wait(smem_u32(&s_mbar[s]), ph);

            const float4* buf = s_buf[s];
            const int rowbase = tile * TILE_ROWS;
            #pragma unroll
            for (int k = 0; k < TILE_CHUNKS / BLOCK; k++) {
                const int j = tid + k * BLOCK;           // chunk within tile
                const float4 v = buf[j];                 // conflict-free LDS.128
                const float m = __ldg(&mask[rowbase + (j >> 3)]);
                acc += m * hsum4(v);
            }
            __syncthreads();   // all threads done reading stage s

            const int inext = i + STAGES;
            if (tid == 0 && inext < n_tiles) {
                const uint32_t mb = smem_u32(&s_mbar[s]);
                mbar_expect_tx(mb, TILE_BYTES);
                bulk_g2s(smem_u32(&s_buf[s][0]),
                         em4 + (size_t)(t0 + inext * GRID) * TILE_CHUNKS,
                         TILE_BYTES, mb);
            }
            if (++s == STAGES) { s = 0; ph ^= 1; }
        }
    }

    // ---- Reduce: warp tree -> block -> global double atomic.
    #pragma unroll
    for (int o = 16; o > 0; o >>= 1)
        acc += __shfl_xor_sync(0xffffffffu, acc, o);

    const int wid = tid >> 5;
    if ((tid & 31) == 0) warp_sums[wid] = acc;
    __syncthreads();

    if (tid == 0) {
        float b = 0.0f;
        #pragma unroll
        for (int i = 0; i < BLOCK / 32; i++) b += warp_sums[i];
        atomicAdd(&g_acc, (double)b);
        __threadfence();
        const unsigned int ticket = atomicInc(&g_count, GRID - 1);
        if (ticket == GRID - 1) {
            out[0] = (float)atomicAdd(&g_acc, 0.0);
            g_acc = 0.0;
        }
    }
}

extern "C" void kernel_launch(void* const* d_in, const int* in_sizes, int n_in,
                              void* d_out, int out_size) {
    const float* emissions   = (const float*)d_in[0];
    const int*   tags        = (const int*)d_in[1];
    const float* mask        = (const float*)d_in[2];
    const float* transitions = (const float*)d_in[3];

    crf_fused_kernel<<<GRID, BLOCK>>>(
        (const float4*)emissions, tags, mask, transitions, (float*)d_out);
}

// round 10
// speedup vs baseline: 1.0367x; 1.0367x over previous
#include <cuda_runtime.h>
#include <cstdint>

// CRF_14379550507279 fixed shapes:
//   emissions (B=512, S=2048, T=32) f32, tags (B,S) i32, mask (B,S) f32,
//   transitions (32,32) f32. Output: scalar f32.
//
// total = sum_{all b,s,t} mask[b,s]*em[b,s,t]                              (phase 2)
//       + sum_b [ (1-mask[b,0])*sum_t em[b,0,t] + sum_t trans[tags[b,0],t] ] (phase 1b)
//       + 32 * sum_{b,s>=1} trans[tags[b,s-1],tags[b,s]] * mask[b,s]        (phase 1a)

#define NTAGS 32
#define B_DIM 512
#define S_DIM 2048
#define BS_ROWS (B_DIM * S_DIM)            // 1048576 rows (128 B each)

#define GRID 296                           // 148 SMs * 2 CTAs
#define BLOCK 288                          // 8 consumer warps + 1 producer warp
#define CONSUMERS 256
#define NC (GRID * CONSUMERS)              // consumer thread count (phase 1)

#define STAGES 6
#define TILE_BYTES 16384                   // 16 KB per stage
#define TILE_CHUNKS 1024                   // float4 per tile
#define TILE_ROWS 128                      // emission rows per tile
#define N_TILES (BS_ROWS / TILE_ROWS)      // 8192
#define DYN_SMEM (STAGES * TILE_BYTES)     // 96 KB pipeline buffer

__device__ double g_acc = 0.0;
__device__ unsigned int g_count = 0;

__device__ __forceinline__ float hsum4(float4 v) {
    return (v.x + v.y) + (v.z + v.w);
}

__device__ __forceinline__ uint32_t smem_u32(const void* p) {
    uint32_t a;
    asm("{ .reg .u64 t; cvta.to.shared.u64 t, %1; cvt.u32.u64 %0, t; }"
        : "=r"(a) : "l"(p));
    return a;
}

__device__ __forceinline__ void mbar_init(uint32_t mbar, uint32_t cnt) {
    asm volatile("mbarrier.init.shared.b64 [%0], %1;" :: "r"(mbar), "r"(cnt) : "memory");
}

__device__ __forceinline__ void mbar_expect_tx(uint32_t mbar, uint32_t bytes) {
    asm volatile("mbarrier.arrive.expect_tx.shared.b64 _, [%0], %1;"
                 :: "r"(mbar), "r"(bytes) : "memory");
}

__device__ __forceinline__ void mbar_arrive(uint32_t mbar) {
    asm volatile("mbarrier.arrive.shared.b64 _, [%0];" :: "r"(mbar) : "memory");
}

__device__ __forceinline__ void mbar_wait(uint32_t mbar, uint32_t parity) {
    uint32_t done;
    asm volatile(
        "{\n\t.reg .pred p;\n\t"
        "mbarrier.try_wait.parity.acquire.cta.shared::cta.b64 p, [%1], %2;\n\t"
        "selp.b32 %0, 1, 0, p;\n\t}"
        : "=r"(done) : "r"(mbar), "r"(parity) : "memory");
    if (!done) {
        asm volatile(
            "{\n\t.reg .pred P1;\n\t"
            "W_%=:\n\t"
            "mbarrier.try_wait.parity.acquire.cta.shared::cta.b64 P1, [%0], %1, 0x989680;\n\t"
            "@P1 bra.uni D_%=;\n\t"
            "bra.uni W_%=;\n\t"
            "D_%=:\n\t}"
            :: "r"(mbar), "r"(parity) : "memory");
    }
}

__device__ __forceinline__ void bulk_g2s(uint32_t dst, const void* src,
                                         uint32_t bytes, uint32_t mbar) {
    asm volatile(
        "cp.async.bulk.shared::cluster.global.mbarrier::complete_tx::bytes "
        "[%0], [%1], %2, [%3];"
        :: "r"(dst), "l"(src), "r"(bytes), "r"(mbar) : "memory");
}

__global__ void __launch_bounds__(BLOCK, 2) crf_fused_kernel(
    const float4* __restrict__ em4,    // B*S*8 float4 chunks
    const int* __restrict__ tags,      // B*S
    const float* __restrict__ mask,    // B*S
    const float* __restrict__ trans,   // 32*32
    float* __restrict__ out)
{
    extern __shared__ __align__(128) float4 s_buf[];      // STAGES*TILE_CHUNKS
    __shared__ float s_trans[NTAGS * NTAGS];
    __shared__ __align__(8) unsigned long long s_full[STAGES];
    __shared__ __align__(8) unsigned long long s_empty[STAGES];
    __shared__ float warp_sums[BLOCK / 32];

    const int tid = threadIdx.x;

    for (int i = tid; i < NTAGS * NTAGS; i += BLOCK)
        s_trans[i] = trans[i];
    if (tid < STAGES) {
        mbar_init(smem_u32(&s_full[tid]), 1);    // flipped by expect_tx+bytes
        mbar_init(smem_u32(&s_empty[tid]), 8);   // one arrive per consumer warp
    }
    __syncthreads();

    // Static tile schedule: CTA owns tiles b, b+GRID, ...  (27 or 28 tiles)
    const int n_tiles = (N_TILES - blockIdx.x + GRID - 1) / GRID;

    float acc = 0.0f;

    if (tid >= CONSUMERS) {
        // ================= PRODUCER WARP (warp 8) =================
        // Prefills all STAGES immediately; thereafter paced by empty arrivals.
        int st = 0, ph = 1;                      // ring convention: first empty-wait passes
        const bool leader = (tid == CONSUMERS);  // lane 0 of warp 8
        for (int i = 0; i < n_tiles; i++) {
            mbar_wait(smem_u32(&s_empty[st]), ph);
            if (leader) {
                const uint32_t fb = smem_u32(&s_full[st]);
                mbar_expect_tx(fb, TILE_BYTES);
                bulk_g2s(smem_u32(&s_buf[st * TILE_CHUNKS]),
                         em4 + (size_t)(blockIdx.x + i * GRID) * TILE_CHUNKS,
                         TILE_BYTES, fb);
            }
            if (++st == STAGES) { st = 0; ph ^= 1; }
        }
    } else {
        // ================= CONSUMER WARPS (0..7) =================
        const int cgid = blockIdx.x * CONSUMERS + tid;

        // ---- Phase 1a: transition steps, branch-free (overlaps TMA prefill).
        for (int row = cgid; row < BS_ROWS; row += NC) {
            const int s = row & (S_DIM - 1);
            const int tc = __ldg(&tags[row]);
            const int tp = __ldg(&tags[(row > 0) ? (row - 1) : 0]);
            const float w = (s == 0) ? 0.0f : __ldg(&mask[row]);
            acc += (float)NTAGS * s_trans[tp * NTAGS + tc] * w;
        }

        // ---- Phase 1b: s==0 specials (512 terms).
        if (cgid < B_DIM) {
            const int row = cgid * S_DIM;
            const int tc = __ldg(&tags[row]);
            const float m = __ldg(&mask[row]);
            float ts = 0.0f;
            #pragma unroll
            for (int t = 0; t < NTAGS; t++) ts += s_trans[tc * NTAGS + t];
            float es = 0.0f;
            const float4* p = em4 + (size_t)row * 8;
            #pragma unroll
            for (int i = 0; i < 8; i++) es += hsum4(__ldg(p + i));
            // phase 2 weights this row by mask[b,0]; reference wants weight 1
            acc += ts + (1.0f - m) * es;
        }

        // ---- Phase 2: drain the pipeline. No __syncthreads; per-warp arrives.
        int st = 0, ph = 0;
        const bool warp_leader = ((tid & 31) == 0);
        for (int i = 0; i < n_tiles; i++) {
            mbar_wait(smem_u32(&s_full[st]), ph);
            const float4* buf = s_buf + st * TILE_CHUNKS;
            const int rowbase = (blockIdx.x + i * GRID) * TILE_ROWS;
            #pragma unroll
            for (int k = 0; k < TILE_CHUNKS / CONSUMERS; k++) {
                const int j = tid + k * CONSUMERS;
                const float4 v = buf[j];                       // conflict-free LDS.128
                const float m = __ldg(&mask[rowbase + (j >> 3)]);
                acc += m * hsum4(v);
            }
            // acc depends on all lanes' LDS results (warp-level scoreboard), so
            // the elected arrive below issues only after the reads completed.
            if (warp_leader) mbar_arrive(smem_u32(&s_empty[st]));
            if (++st == STAGES) { st = 0; ph ^= 1; }
        }
    }

    // ---- Reduce: warp tree -> block -> global double atomic.
    #pragma unroll
    for (int o = 16; o > 0; o >>= 1)
        acc += __shfl_xor_sync(0xffffffffu, acc, o);

    const int wid = tid >> 5;
    if ((tid & 31) == 0) warp_sums[wid] = acc;
    __syncthreads();

    if (tid == 0) {
        float b = 0.0f;
        #pragma unroll
        for (int i = 0; i < BLOCK / 32; i++) b += warp_sums[i];
        atomicAdd(&g_acc, (double)b);
        __threadfence();
        const unsigned int ticket = atomicInc(&g_count, GRID - 1);
        if (ticket == GRID - 1) {
            out[0] = (float)atomicAdd(&g_acc, 0.0);
            g_acc = 0.0;
        }
    }
}

extern "C" void kernel_launch(void* const* d_in, const int* in_sizes, int n_in,
                              void* d_out, int out_size) {
    const float* emissions   = (const float*)d_in[0];
    const int*   tags        = (const int*)d_in[1];
    const float* mask        = (const float*)d_in[2];
    const float* transitions = (const float*)d_in[3];

    // 96 KB dynamic smem pipeline buffer (idempotent attribute set; not a stream op)
    cudaFuncSetAttribute(crf_fused_kernel,
                         cudaFuncAttributeMaxDynamicSharedMemorySize, DYN_SMEM);

    crf_fused_kernel<<<GRID, BLOCK, DYN_SMEM>>>(
        (const float4*)emissions, tags, mask, transitions, (float*)d_out);
}

// round 13
// speedup vs baseline: 1.3532x; 1.3053x over previous
#include <cuda_runtime.h>
#include <cstdint>

// CRF_14379550507279 fixed shapes:
//   emissions (B=512, S=2048, T=32) f32, tags (B,S) i32, mask (B,S) f32,
//   transitions (32,32) f32. Output: scalar f32.
//
// total = sum_{all b,s,t} mask[b,s]*em[b,s,t]                                (stream blocks)
//       + sum_b [ (1-mask[b,0])*sum_t em[b,0,t] + sum_t trans[tags[b,0],t] ] (p1 blocks)
//       + 32 * sum_{b,s>=1} trans[tags[b,s-1],tags[b,s]] * mask[b,s]         (p1 blocks)

#define NTAGS 32
#define B_DIM 512
#define S_DIM 2048
#define BS_ROWS (B_DIM * S_DIM)              // 1048576 rows of 128 B
#define TOTAL_C8 (BS_ROWS * 4)               // 4194304 32-byte chunks

#define GRID 1184                            // 148 SMs * 8 CTAs, one even wave
#define BLOCK 128

#define P1_BLOCKS 128                        // dedicated transition blocks
#define P1T (P1_BLOCKS * BLOCK)              // 16384 threads
#define P1_ITERS (BS_ROWS / P1T)             // 64, exact

#define SB (GRID - P1_BLOCKS)                // 1056 stream blocks
#define NT (SB * BLOCK)                      // 135168 stream threads
#define NTR (NT / 4)                         // row stride per body step

__device__ double g_acc = 0.0;
__device__ unsigned int g_count = 0;

__device__ __forceinline__ float hsum4(float4 v) {
    return (v.x + v.y) + (v.z + v.w);
}

struct f8 { float4 a, b; };

// 256-bit streaming read: bypass L1, evict-first in L2 (no reuse)
__device__ __forceinline__ f8 ldg_stream256(const void* p) {
    f8 v;
    asm("ld.global.nc.L2::evict_first.v8.b32 "
        "{%0,%1,%2,%3,%4,%5,%6,%7}, [%8];"
        : "=f"(v.a.x), "=f"(v.a.y), "=f"(v.a.z), "=f"(v.a.w),
          "=f"(v.b.x), "=f"(v.b.y), "=f"(v.b.z), "=f"(v.b.w)
        : "l"(p));
    return v;
}

__device__ __forceinline__ float hsum8(f8 v) {
    return hsum4(v.a) + hsum4(v.b);
}

__global__ void __launch_bounds__(BLOCK, 8) crf_fused_kernel(
    const float* __restrict__ em,      // B*S*32 floats
    const int* __restrict__ tags,      // B*S
    const float* __restrict__ mask,    // B*S
    const float* __restrict__ trans,   // 32*32
    float* __restrict__ out)
{
    __shared__ float s_trans[NTAGS * NTAGS];
    __shared__ float warp_sums[BLOCK / 32];

    const int tid = threadIdx.x;
    float acc = 0.0f;

    if (blockIdx.x < P1_BLOCKS) {
        // ================= PHASE-1 BLOCKS: transition terms =================
        for (int i = tid; i < NTAGS * NTAGS; i += BLOCK)
            s_trans[i] = trans[i];
        __syncthreads();

        const int p1tid = blockIdx.x * BLOCK + tid;
        // s = row & 2047 is invariant per thread (P1T multiple of S_DIM)
        const int s = p1tid & (S_DIM - 1);
        const float sw = (s == 0) ? 0.0f : 1.0f;

        #pragma unroll 4
        for (int k = 0; k < P1_ITERS; k++) {
            const int row = p1tid + k * P1T;
            const int tc = __ldg(&tags[row]);
            const int tp = __ldg(&tags[(row > 0) ? (row - 1) : 0]);
            const float w = sw * __ldg(&mask[row]);
            // scalar trans broadcast over T columns -> counted NTAGS times
            acc += (float)NTAGS * s_trans[tp * NTAGS + tc] * w;
        }

        // s==0 specials: 512 terms, one thread per batch
        if (p1tid < B_DIM) {
            const int row = p1tid * S_DIM;
            const int tc = __ldg(&tags[row]);
            const float m = __ldg(&mask[row]);
            float ts = 0.0f;
            #pragma unroll
            for (int t = 0; t < NTAGS; t++) ts += s_trans[tc * NTAGS + t];
            float es = 0.0f;
            const float4* p = (const float4*)(em + (size_t)row * 32);
            #pragma unroll
            for (int i = 0; i < 8; i++) es += hsum4(__ldg(p + i));
            // stream blocks weight this row by mask[b,0]; reference wants 1
            acc += ts + (1.0f - m) * es;
        }
    } else {
        // ============ STREAM BLOCKS: masked emission sum (LDG.256) ============
        const int stid = (blockIdx.x - P1_BLOCKS) * BLOCK + tid;

        float a0 = 0.0f, a1 = 0.0f, a2 = 0.0f, a3 = 0.0f;
        int q = stid;                  // 32-byte chunk index
        int mr = stid >> 2;            // row index (4 chunks per row)
        for (; q + 3 * NT < TOTAL_C8; q += 4 * NT, mr += 4 * NTR) {
            // front-batch 4 independent LDG.256 + 4 broadcast mask LDG.32
            const f8 v0 = ldg_stream256(em + (size_t)(q + 0 * NT) * 8);
            const f8 v1 = ldg_stream256(em + (size_t)(q + 1 * NT) * 8);
            const f8 v2 = ldg_stream256(em + (size_t)(q + 2 * NT) * 8);
            const f8 v3 = ldg_stream256(em + (size_t)(q + 3 * NT) * 8);
            const float m0 = __ldg(&mask[mr + 0 * NTR]);
            const float m1 = __ldg(&mask[mr + 1 * NTR]);
            const float m2 = __ldg(&mask[mr + 2 * NTR]);
            const float m3 = __ldg(&mask[mr + 3 * NTR]);
            a0 += m0 * hsum8(v0);
            a1 += m1 * hsum8(v1);
            a2 += m2 * hsum8(v2);
            a3 += m3 * hsum8(v3);
        }
        for (; q < TOTAL_C8; q += NT, mr += NTR) {
            const f8 v = ldg_stream256(em + (size_t)q * 8);
            a0 += __ldg(&mask[mr]) * hsum8(v);
        }
        acc = (a0 + a1) + (a2 + a3);
    }

    // ---- Reduce: warp tree -> block -> global double atomic.
    #pragma unroll
    for (int o = 16; o > 0; o >>= 1)
        acc += __shfl_xor_sync(0xffffffffu, acc, o);

    const int wid = tid >> 5;
    if ((tid & 31) == 0) warp_sums[wid] = acc;
    __syncthreads();

    if (tid == 0) {
        float b = 0.0f;
        #pragma unroll
        for (int i = 0; i < BLOCK / 32; i++) b += warp_sums[i];
        atomicAdd(&g_acc, (double)b);
        __threadfence();
        // last block finalizes: write scalar, reset accumulator for next replay
        const unsigned int ticket = atomicInc(&g_count, GRID - 1);
        if (ticket == GRID - 1) {
            out[0] = (float)atomicAdd(&g_acc, 0.0);
            g_acc = 0.0;
        }
    }
}

extern "C" void kernel_launch(void* const* d_in, const int* in_sizes, int n_in,
                              void* d_out, int out_size) {
    const float* emissions   = (const float*)d_in[0];
    const int*   tags        = (const int*)d_in[1];
    const float* mask        = (const float*)d_in[2];
    const float* transitions = (const float*)d_in[3];

    crf_fused_kernel<<<GRID, BLOCK>>>(
        emissions, tags, mask, transitions, (float*)d_out);
}